// round 1
// baseline (speedup 1.0000x reference)
#include <cuda_runtime.h>
#include <math.h>

#define BATCH  2
#define SEQ    2048
#define DMODEL 1024
#define DINNER 2048
#define DSTATE 16
#define DTRANK 64
#define NTOK   (BATCH*SEQ)     /* 4096 tokens */
#define XDN    96              /* dt_rank + 2*d_state */

// ---------------- scratch (static device globals; no allocation) ----------
__device__ float g_xn[NTOK*DMODEL];            // 16 MB
__device__ float g_xz[NTOK*2*DINNER];          // 64 MB
__device__ float g_u[NTOK*DINNER];             // 32 MB
__device__ float g_xdbl[NTOK*XDN];             // 1.5 MB
__device__ float g_delta[NTOK*DINNER];         // 32 MB
__device__ float g_y[NTOK*DINNER];             // 32 MB

// ---------------- helpers ----------------
__device__ __forceinline__ float softplus_f(float x){
    return (x > 20.f) ? x : log1pf(expf(x));
}
__device__ __forceinline__ float gelu_f(float x){
    return 0.5f * x * (1.f + erff(x * 0.70710678118654752440f));
}
__device__ __forceinline__ float silu_f(float x){
    return x * (1.f / (1.f + __expf(-x)));
}

// ---------------- LayerNorm: one block per token ----------------
__global__ void __launch_bounds__(256) ln_kernel(const float* __restrict__ x,
                                                 const float* __restrict__ w,
                                                 const float* __restrict__ b,
                                                 float* __restrict__ out)
{
    int row = blockIdx.x;
    int tid = threadIdx.x;
    const float4* xr = reinterpret_cast<const float4*>(x + (size_t)row*DMODEL);
    float4 v = xr[tid];
    float s = v.x+v.y+v.z+v.w;
    float q = v.x*v.x+v.y*v.y+v.z*v.z+v.w*v.w;
    #pragma unroll
    for (int o=16;o>0;o>>=1){
        s += __shfl_down_sync(0xffffffffu, s, o);
        q += __shfl_down_sync(0xffffffffu, q, o);
    }
    __shared__ float ss[8], sq[8];
    __shared__ float mu_s, inv_s;
    int wp = tid>>5, ln = tid&31;
    if (ln==0){ ss[wp]=s; sq[wp]=q; }
    __syncthreads();
    if (tid==0){
        float ts=0.f, tq=0.f;
        #pragma unroll
        for (int i=0;i<8;i++){ ts+=ss[i]; tq+=sq[i]; }
        float mu  = ts * (1.f/DMODEL);
        float var = tq * (1.f/DMODEL) - mu*mu;
        mu_s = mu; inv_s = rsqrtf(var + 1e-5f);
    }
    __syncthreads();
    float mu = mu_s, inv = inv_s;
    float4 wv = reinterpret_cast<const float4*>(w)[tid];
    float4 bv = reinterpret_cast<const float4*>(b)[tid];
    float4 o;
    o.x = (v.x-mu)*inv*wv.x + bv.x;
    o.y = (v.y-mu)*inv*wv.y + bv.y;
    o.z = (v.z-mu)*inv*wv.z + bv.z;
    o.w = (v.w-mu)*inv*wv.w + bv.w;
    reinterpret_cast<float4*>(out + (size_t)row*DMODEL)[tid] = o;
}

// ---------------- SGEMM 128x128x8, 256 threads, 8x8 per thread -----------
// C[M,N] = A[M,K] @ B[K,N], all row-major, M,N multiples of 128, K mult of 8.
// EPI: 0 = plain, 1 = softplus(acc + bias[col]), 2 = gelu(acc) + res[row,col]
template<int EPI>
__global__ void __launch_bounds__(256) sgemm128(const float* __restrict__ A,
                                                const float* __restrict__ B,
                                                float* __restrict__ C,
                                                int M, int N, int K,
                                                int lda, int ldb, int ldc,
                                                const float* __restrict__ bias,
                                                const float* __restrict__ res,
                                                int ldres)
{
    __shared__ float As[8][128];
    __shared__ float Bs[8][128];
    const int tid = threadIdx.x;
    const int bm = blockIdx.y*128, bn = blockIdx.x*128;
    const int ty = tid>>4, tx = tid&15;
    const int arow = tid>>1,  acol = (tid&1)*4;
    const int brow = tid>>5,  bcol = (tid&31)*4;

    const float* Ap = A + (size_t)(bm+arow)*lda + acol;   // +k along row
    const float* Bp = B + (size_t)brow*ldb + bn + bcol;   // +k*ldb down

    float4 af = *(const float4*)Ap;
    float4 bf = *(const float4*)Bp;

    float acc[8][8];
    #pragma unroll
    for (int i=0;i<8;i++)
        #pragma unroll
        for (int j=0;j<8;j++) acc[i][j]=0.f;

    for (int k0=0; k0<K; k0+=8){
        As[acol+0][arow]=af.x; As[acol+1][arow]=af.y;
        As[acol+2][arow]=af.z; As[acol+3][arow]=af.w;
        *(float4*)&Bs[brow][bcol] = bf;
        __syncthreads();
        if (k0+8 < K){
            af = *(const float4*)(Ap + (k0+8));
            bf = *(const float4*)(Bp + (size_t)(k0+8)*ldb);
        }
        #pragma unroll
        for (int k=0;k<8;k++){
            float ar[8], br[8];
            *(float4*)&ar[0] = *(const float4*)&As[k][ty*8];
            *(float4*)&ar[4] = *(const float4*)&As[k][ty*8+4];
            *(float4*)&br[0] = *(const float4*)&Bs[k][tx*8];
            *(float4*)&br[4] = *(const float4*)&Bs[k][tx*8+4];
            #pragma unroll
            for (int i=0;i<8;i++)
                #pragma unroll
                for (int j=0;j<8;j++)
                    acc[i][j] = fmaf(ar[i], br[j], acc[i][j]);
        }
        __syncthreads();
    }

    #pragma unroll
    for (int i=0;i<8;i++){
        int r = bm + ty*8 + i;
        float vals[8];
        #pragma unroll
        for (int j=0;j<8;j++){
            float v = acc[i][j];
            int c = bn + tx*8 + j;
            if (EPI==1)      v = softplus_f(v + bias[c]);
            else if (EPI==2) v = gelu_f(v) + res[(size_t)r*ldres + c];
            vals[j] = v;
        }
        float* cp = C + (size_t)r*ldc + bn + tx*8;
        *(float4*)cp     = *(float4*)&vals[0];
        *(float4*)(cp+4) = *(float4*)&vals[4];
    }
}

// ---------------- depthwise causal conv (width 4) + SiLU -----------------
// u[b,t,d] = silu( sum_j xz[b, t-3+j, d] * conv_w[d, j] + conv_b[d] )
__global__ void __launch_bounds__(256) conv_silu_kernel(const float* __restrict__ xz,
                                                        const float* __restrict__ cw,
                                                        const float* __restrict__ cb,
                                                        float* __restrict__ u)
{
    int lin = blockIdx.x*256 + threadIdx.x;        // over NTOK * DINNER/4
    int d4  = lin & (DINNER/4 - 1);
    int tok = lin >> 9;                            // DINNER/4 = 512
    int t   = tok & (SEQ-1);
    int d   = d4*4;

    float4 acc = *(const float4*)(cb + d);
    float w0[4], w1[4], w2[4], w3[4];
    *(float4*)w0 = *(const float4*)(cw + (size_t)(d+0)*4);
    *(float4*)w1 = *(const float4*)(cw + (size_t)(d+1)*4);
    *(float4*)w2 = *(const float4*)(cw + (size_t)(d+2)*4);
    *(float4*)w3 = *(const float4*)(cw + (size_t)(d+3)*4);

    const float* base = xz + (size_t)tok*(2*DINNER) + d;
    #pragma unroll
    for (int j=0;j<4;j++){
        int tt = t - 3 + j;
        if (tt >= 0){
            float4 xv = *(const float4*)(base + (ptrdiff_t)(j-3)*(2*DINNER));
            acc.x = fmaf(xv.x, w0[j], acc.x);
            acc.y = fmaf(xv.y, w1[j], acc.y);
            acc.z = fmaf(xv.z, w2[j], acc.z);
            acc.w = fmaf(xv.w, w3[j], acc.w);
        }
    }
    float4 o;
    o.x = silu_f(acc.x); o.y = silu_f(acc.y);
    o.z = silu_f(acc.z); o.w = silu_f(acc.w);
    *(float4*)(u + (size_t)tok*DINNER + d) = o;
}

// ---------------- skinny GEMM: x_dbl = u @ W_x  (4096 x 96 x 2048) -------
__global__ void __launch_bounds__(256) gemm_xdbl_kernel(const float* __restrict__ A,
                                                        const float* __restrict__ B,
                                                        float* __restrict__ C)
{
    __shared__ float As[32][65];
    __shared__ float Bs[32][100];
    int tid = threadIdx.x;
    int bm  = blockIdx.x*64;
    int ty  = tid>>4, tx = tid&15;
    float acc[4][6];
    #pragma unroll
    for (int i=0;i<4;i++)
        #pragma unroll
        for (int j=0;j<6;j++) acc[i][j]=0.f;

    for (int k0=0;k0<DINNER;k0+=32){
        #pragma unroll
        for (int i=0;i<2;i++){
            int lin = tid + i*256;                 // 512 float4 of A tile
            int m = lin>>3, k4 = (lin&7)*4;
            float4 v = *(const float4*)(A + (size_t)(bm+m)*DINNER + k0 + k4);
            As[k4+0][m]=v.x; As[k4+1][m]=v.y; As[k4+2][m]=v.z; As[k4+3][m]=v.w;
        }
        #pragma unroll
        for (int i=0;i<3;i++){
            int lin = tid + i*256;                 // 768 float4 of B tile
            int kr = lin/24, c4 = (lin%24)*4;
            float4 v = *(const float4*)(B + (size_t)(k0+kr)*XDN + c4);
            *(float4*)&Bs[kr][c4] = v;
        }
        __syncthreads();
        #pragma unroll
        for (int k=0;k<32;k++){
            float a[4], bb[6];
            #pragma unroll
            for (int i=0;i<4;i++) a[i]=As[k][ty*4+i];
            #pragma unroll
            for (int j=0;j<6;j++) bb[j]=Bs[k][tx*6+j];
            #pragma unroll
            for (int i=0;i<4;i++)
                #pragma unroll
                for (int j=0;j<6;j++)
                    acc[i][j] = fmaf(a[i], bb[j], acc[i][j]);
        }
        __syncthreads();
    }
    #pragma unroll
    for (int i=0;i<4;i++)
        #pragma unroll
        for (int j=0;j<6;j++)
            C[(size_t)(bm+ty*4+i)*XDN + tx*6 + j] = acc[i][j];
}

// ---------------- selective scan (fused gating output) -------------------
// Warp layout: lanes 0-15 = states of channel d0, lanes 16-31 = channel d0+1.
// y[b,t,d] = (C_t . h_t + u*D) * silu(z)
__global__ void __launch_bounds__(256) scan_kernel(const float* __restrict__ delta,
                                                   const float* __restrict__ u,
                                                   const float* __restrict__ xdbl,
                                                   const float* __restrict__ xz,
                                                   const float* __restrict__ A_log,
                                                   const float* __restrict__ D_skip,
                                                   float* __restrict__ y)
{
    int b    = blockIdx.y;
    int tid  = threadIdx.x;
    int warp = tid>>5;
    int lane = tid&31;
    int half = lane>>4;
    int s    = lane&15;
    int d    = blockIdx.x*16 + warp*2 + half;

    float Aval = -expf(A_log[(size_t)d*DSTATE + s]);
    float Dv   = D_skip[d];

    const float* drow = delta + (size_t)b*SEQ*DINNER + d;
    const float* urow = u     + (size_t)b*SEQ*DINNER + d;
    const float* zrow = xz    + (size_t)b*SEQ*(2*DINNER) + DINNER + d;
    const float* xb   = xdbl  + (size_t)b*SEQ*XDN + DTRANK + s;
    float*       yrow = y     + (size_t)b*SEQ*DINNER + d;

    float h = 0.f;
    for (int t=0; t<SEQ; t++){
        float dlt = __ldg(drow + (size_t)t*DINNER);
        float uu  = __ldg(urow + (size_t)t*DINNER);
        float Bv  = __ldg(xb + (size_t)t*XDN);
        float Cv  = __ldg(xb + (size_t)t*XDN + DSTATE);
        float dA  = __expf(dlt * Aval);
        h = fmaf(dA, h, (dlt*uu)*Bv);
        float yp = h * Cv;
        yp += __shfl_xor_sync(0xffffffffu, yp, 1);
        yp += __shfl_xor_sync(0xffffffffu, yp, 2);
        yp += __shfl_xor_sync(0xffffffffu, yp, 4);
        yp += __shfl_xor_sync(0xffffffffu, yp, 8);
        if (s == 0){
            float zz = __ldg(zrow + (size_t)t*(2*DINNER));
            yrow[(size_t)t*DINNER] = (yp + uu*Dv) * silu_f(zz);
        }
    }
}

// ---------------- launch ----------------
extern "C" void kernel_launch(void* const* d_in, const int* in_sizes, int n_in,
                              void* d_out, int out_size)
{
    const float* x      = (const float*)d_in[0];
    const float* ln_w   = (const float*)d_in[1];
    const float* ln_b   = (const float*)d_in[2];
    const float* W_in   = (const float*)d_in[3];
    const float* conv_w = (const float*)d_in[4];
    const float* conv_b = (const float*)d_in[5];
    const float* W_x    = (const float*)d_in[6];
    const float* W_dt   = (const float*)d_in[7];
    const float* b_dt   = (const float*)d_in[8];
    const float* A_log  = (const float*)d_in[9];
    const float* D_skip = (const float*)d_in[10];
    const float* W_out  = (const float*)d_in[11];
    float* out = (float*)d_out;

    float *xn, *xz, *u, *xdbl, *delta, *y;
    cudaGetSymbolAddress((void**)&xn,    g_xn);
    cudaGetSymbolAddress((void**)&xz,    g_xz);
    cudaGetSymbolAddress((void**)&u,     g_u);
    cudaGetSymbolAddress((void**)&xdbl,  g_xdbl);
    cudaGetSymbolAddress((void**)&delta, g_delta);
    cudaGetSymbolAddress((void**)&y,     g_y);

    // 1) LayerNorm
    ln_kernel<<<NTOK, 256>>>(x, ln_w, ln_b, xn);

    // 2) xz = xn @ W_in   [4096 x 4096 x 1024]
    sgemm128<0><<<dim3((2*DINNER)/128, NTOK/128), 256>>>(
        xn, W_in, xz, NTOK, 2*DINNER, DMODEL, DMODEL, 2*DINNER, 2*DINNER,
        nullptr, nullptr, 0);

    // 3) depthwise causal conv + silu -> u
    conv_silu_kernel<<<(NTOK*(DINNER/4))/256, 256>>>(xz, conv_w, conv_b, u);

    // 4) x_dbl = u @ W_x  [4096 x 96 x 2048]
    gemm_xdbl_kernel<<<NTOK/64, 256>>>(u, W_x, xdbl);

    // 5) delta = softplus(dt @ W_dt + b_dt)  [4096 x 2048 x 64], dt = x_dbl[:, :64]
    sgemm128<1><<<dim3(DINNER/128, NTOK/128), 256>>>(
        xdbl, W_dt, delta, NTOK, DINNER, DTRANK, XDN, DINNER, DINNER,
        b_dt, nullptr, 0);

    // 6) selective scan + gating -> y
    scan_kernel<<<dim3(DINNER/16, BATCH), 256>>>(delta, u, xdbl, xz, A_log, D_skip, y);

    // 7) out = gelu(y @ W_out) + x  [4096 x 1024 x 2048]
    sgemm128<2><<<dim3(DMODEL/128, NTOK/128), 256>>>(
        y, W_out, out, NTOK, DMODEL, DINNER, DINNER, DMODEL, DMODEL,
        nullptr, x, DMODEL);
}